// round 10
// baseline (speedup 1.0000x reference)
#include <cuda_runtime.h>

// Fixed problem shapes (from reference setup_inputs)
#define N_L    4096
#define NT     16
#define NV     4
#define NH_SZ  9
#define KC     144          // candidates per (cell,target)
#define CAP    8            // per-target recovery list capacity

#define MASK_VALUE   1.0e6f
#define CUTOFF_DIST  0.01f
#define BIG          3.0e38f

// Insert value d into sorted triple (s0<=s1<=s2). 5 FMNMX, exact.
#define VINS(d, s0, s1, s2) do {                     \
    float _t1 = fmaxf(s0, (d)); s0 = fminf(s0, (d)); \
    float _t2 = fmaxf(s1, _t1); s1 = fminf(s1, _t1); \
    s2 = fminf(s2, _t2);                             \
} while (0)

// Lowest-3 of two sorted triples -> (c0<=c1<=c2). 9 FMNMX, exact.
#define MERGE3(a0,a1,a2,b0,b1,b2,c0,c1,c2) do {      \
    c0 = fminf(a0, b0);                              \
    float _x = fmaxf(a0, b0);                        \
    c1 = fminf(_x, fminf(a1, b1));                   \
    c2 = fminf(fminf(a2, b2),                        \
               fminf(fmaxf(a1, b0), fmaxf(a0, b1))); \
} while (0)

// Lexicographic u64-key insert into 3 smallest.
__device__ __forceinline__ void kins(unsigned long long key,
    unsigned long long& q0, unsigned long long& q1, unsigned long long& q2) {
    bool b0 = key < q0, b1 = key < q1, b2 = key < q2;
    unsigned long long n2 = b1 ? q1 : (b2 ? key : q2);
    unsigned long long n1 = b0 ? q0 : (b1 ? key : q1);
    q0 = b0 ? key : q0;
    q1 = n1; q2 = n2;
}

// (value,index) lex insert for slow path.
__device__ __forceinline__ void ins_lex(float d, int k,
    float& d0, int& k0, float& d1, int& k1, float& d2, int& k2) {
    bool b0 = (d < d0) || (d == d0 && k < k0);
    bool b1 = (d < d1) || (d == d1 && k < k1);
    bool b2 = (d < d2) || (d == d2 && k < k2);
    float nd2 = b1 ? d1 : (b2 ? d : d2);  int nk2 = b1 ? k1 : (b2 ? k : k2);
    float nd1 = b0 ? d0 : (b1 ? d : d1);  int nk1 = b0 ? k0 : (b1 ? k : k1);
    d0 = b0 ? d : d0;  k0 = b0 ? k : k0;
    d1 = nd1; k1 = nk1; d2 = nd2; k2 = nk2;
}

__global__ __launch_bounds__(128, 12)
void interp_kernel(const float* __restrict__ x,
                   const float* __restrict__ mask,
                   const float* __restrict__ dist,
                   const int*   __restrict__ nh_idx,
                   float*       __restrict__ out) {
    __shared__ unsigned long long slist[NT][CAP];    // warp-private recovery lists
    __shared__ int scnt[NT];

    const int c    = blockIdx.x;
    const int tid  = threadIdx.x;
    const int lane = tid & 31;
    const int w    = tid >> 5;
    const int t    = w * 4 + (lane >> 3);   // 8 lanes per target, warp-aligned
    const int sub  = lane & 7;

    if (tid < NT) scnt[tid] = 0;

    // ---- dist candidates straight into registers (coalesced float4) ----
    const float4* drow4 = (const float4*)(dist + (size_t)c * (NT * KC) + t * KC);
    float4 v0 = drow4[sub];
    float4 v1 = drow4[sub + 8];
    float4 v2 = drow4[sub + 16];
    float4 v3 = drow4[sub + 24];
    float4 v4 = make_float4(BIG, BIG, BIG, BIG);
    if (sub < 4) v4 = drow4[sub + 32];

    // ---- mask-zero check only (no feature staging) ----
    bool any = false;
    const float4* m4p = (const float4*)mask;
    #pragma unroll
    for (int i = tid; i < KC; i += 128) {
        int nc = nh_idx[c * NH_SZ + (i >> 4)];
        float4 mv = m4p[nc * 16 + (i & 15)];
        any |= (mv.x != 0.f) | (mv.y != 0.f) | (mv.z != 0.f) | (mv.w != 0.f);
    }

    // ---- speculative value-only scan, 4 ILP streams ----
    float ax = BIG, bx = BIG, cx = BIG;
    float ay = BIG, by = BIG, cy = BIG;
    float az = BIG, bz = BIG, cz = BIG;
    float aw = BIG, bw = BIG, cw = BIG;
    VINS(v0.x, ax, bx, cx); VINS(v0.y, ay, by, cy);
    VINS(v0.z, az, bz, cz); VINS(v0.w, aw, bw, cw);
    VINS(v1.x, ax, bx, cx); VINS(v1.y, ay, by, cy);
    VINS(v1.z, az, bz, cz); VINS(v1.w, aw, bw, cw);
    VINS(v2.x, ax, bx, cx); VINS(v2.y, ay, by, cy);
    VINS(v2.z, az, bz, cz); VINS(v2.w, aw, bw, cw);
    VINS(v3.x, ax, bx, cx); VINS(v3.y, ay, by, cy);
    VINS(v3.z, az, bz, cz); VINS(v3.w, aw, bw, cw);
    VINS(v4.x, ax, bx, cx); VINS(v4.y, ay, by, cy);
    VINS(v4.z, az, bz, cz); VINS(v4.w, aw, bw, cw);

    float mx0, mx1, mx2, my0, my1, my2;
    MERGE3(ax, bx, cx, ay, by, cy, mx0, mx1, mx2);
    MERGE3(az, bz, cz, aw, bw, cw, my0, my1, my2);
    float d0, d1, d2;
    MERGE3(mx0, mx1, mx2, my0, my1, my2, d0, d1, d2);

    // ---- merge across the 8 threads of this target ----
    #pragma unroll
    for (int m = 1; m < 8; m <<= 1) {
        float p0 = __shfl_xor_sync(0xffffffffu, d0, m);
        float p1 = __shfl_xor_sync(0xffffffffu, d1, m);
        float p2 = __shfl_xor_sync(0xffffffffu, d2, m);
        float e0, e1, e2;
        MERGE3(d0, d1, d2, p0, p1, p2, e0, e1, e2);
        d0 = e0; d1 = e1; d2 = e2;
    }

    // single barrier: reduce the mask flag (also orders scnt init vs pushes)
    int bad = __syncthreads_or(any ? 1 : 0);

    if (!bad) {
        // ================= FAST PATH (mask == 0) =================
        // exact index recovery: per-component predicated pushes of all
        // candidates <= exact 3rd-smallest (values referenced BY NAME).
        #define TRYC(val, kk) do {                                           \
            if ((val) <= d2) {                                               \
                int _i = atomicAdd(&scnt[t], 1);                             \
                if (_i < CAP)                                                \
                    slist[t][_i] = ((unsigned long long)__float_as_uint(val) \
                                    << 8) | (unsigned)(kk);                  \
            } } while (0)
        const int kb = 4 * sub;
        TRYC(v0.x, kb);       TRYC(v0.y, kb + 1);
        TRYC(v0.z, kb + 2);   TRYC(v0.w, kb + 3);
        TRYC(v1.x, kb + 32);  TRYC(v1.y, kb + 33);
        TRYC(v1.z, kb + 34);  TRYC(v1.w, kb + 35);
        TRYC(v2.x, kb + 64);  TRYC(v2.y, kb + 65);
        TRYC(v2.z, kb + 66);  TRYC(v2.w, kb + 67);
        TRYC(v3.x, kb + 96);  TRYC(v3.y, kb + 97);
        TRYC(v3.z, kb + 98);  TRYC(v3.w, kb + 99);
        if (sub < 4) {
            TRYC(v4.x, kb + 128); TRYC(v4.y, kb + 129);
            TRYC(v4.z, kb + 130); TRYC(v4.w, kb + 131);
        }
        #undef TRYC
        __syncwarp();   // pushes for target t all come from this warp

        if (sub < NV) {
            const int v = sub;
            int n = scnt[t];
            unsigned long long q0 = ~0ull, q1 = ~0ull, q2 = ~0ull;
            if (n <= CAP) {
                for (int i = 0; i < n; i++)
                    kins(slist[t][i], q0, q1, q2);
            } else {
                // degenerate tie overflow: exact full rescan from global
                const float* row = dist + (size_t)c * (NT * KC) + t * KC;
                for (int k = 0; k < KC; k++) {
                    unsigned long long key =
                        ((unsigned long long)__float_as_uint(row[k]) << 8)
                        | (unsigned)k;
                    kins(key, q0, q1, q2);
                }
            }
            float f0 = __uint_as_float((unsigned)(q0 >> 8));
            float f1 = __uint_as_float((unsigned)(q1 >> 8));
            float f2 = __uint_as_float((unsigned)(q2 >> 8));
            int   i0 = (int)(q0 & 0xFF), i1 = (int)(q1 & 0xFF),
                  i2 = (int)(q2 & 0xFF);

            // direct global feature loads (nh_idx / x are L1/L2-hot)
            const int* nh = nh_idx + c * NH_SZ;
            float g0 = x[(nh[i0 >> 4] * 16 + (i0 & 15)) * NV + v];
            float g1 = x[(nh[i1 >> 4] * 16 + (i1 & 15)) * NV + v];
            float g2 = x[(nh[i2 >> 4] * 16 + (i2 & 15)) * NV + v];

            float c0 = fmaxf(f0, CUTOFF_DIST);
            float c1 = fmaxf(f1, CUTOFF_DIST);
            float c2 = fmaxf(f2, CUTOFF_DIST);
            float w0 = c1 * c2, w1 = c0 * c2, w2 = c0 * c1;
            w0 *= w0; w1 *= w1; w2 *= w2;
            out[(size_t)c * (NT * NV) + t * NV + v] =
                (g0 * w0 + g1 * w1 + g2 * w2) / (w0 + w1 + w2);
        }
    } else {
        // ================= SLOW PATH (general mask) =================
        if (tid < NT * NV) {
            const int tt = tid >> 2;
            const int v  = tid & 3;
            const float* dr = dist + (size_t)c * (NT * KC) + tt * KC;
            const int* nh = nh_idx + c * NH_SZ;
            float s0 = BIG, s1 = BIG, s2 = BIG;
            int   k0 = 0,   k1 = 0,   k2 = 0;
            for (int k = 0; k < KC; k++) {
                int nc = nh[k >> 4];
                float mk = mask[(nc * 16 + (k & 15)) * NV + v] * MASK_VALUE;
                float d  = dr[k] + mk;
                ins_lex(d, k, s0, k0, s1, k1, s2, k2);
            }
            float c0 = fmaxf(s0, CUTOFF_DIST);
            float c1 = fmaxf(s1, CUTOFF_DIST);
            float c2 = fmaxf(s2, CUTOFF_DIST);
            float w0 = c1 * c2, w1 = c0 * c2, w2 = c0 * c1;
            w0 *= w0; w1 *= w1; w2 *= w2;
            float g0 = x[(nh[k0 >> 4] * 16 + (k0 & 15)) * NV + v];
            float g1 = x[(nh[k1 >> 4] * 16 + (k1 & 15)) * NV + v];
            float g2 = x[(nh[k2 >> 4] * 16 + (k2 & 15)) * NV + v];
            out[(size_t)c * (NT * NV) + tt * NV + v] =
                (g0 * w0 + g1 * w1 + g2 * w2) / (w0 + w1 + w2);
        }
    }
}

extern "C" void kernel_launch(void* const* d_in, const int* in_sizes, int n_in,
                              void* d_out, int out_size) {
    const float* x      = (const float*)d_in[0];
    const float* mask   = (const float*)d_in[1];
    const float* dist   = (const float*)d_in[2];
    const int*   nh_idx = (const int*)  d_in[3];
    float*       out    = (float*)d_out;

    interp_kernel<<<N_L, 128>>>(x, mask, dist, nh_idx, out);
}

// round 11
// speedup vs baseline: 1.0288x; 1.0288x over previous
#include <cuda_runtime.h>

// Fixed problem shapes (from reference setup_inputs)
#define N_L    4096
#define NT     16
#define NV     4
#define NH_SZ  9
#define KC     144          // candidates per (cell,target)
#define CAP    8            // per-target recovery list capacity

#define MASK_VALUE   1.0e6f
#define CUTOFF_DIST  0.01f
#define BIG          3.0e38f

// Insert value d into sorted triple (s0<=s1<=s2). 5 FMNMX, exact.
#define VINS(d, s0, s1, s2) do {                     \
    float _t1 = fmaxf(s0, (d)); s0 = fminf(s0, (d)); \
    float _t2 = fmaxf(s1, _t1); s1 = fminf(s1, _t1); \
    s2 = fminf(s2, _t2);                             \
} while (0)

// Lowest-3 of two sorted triples -> (c0<=c1<=c2). 9 FMNMX, exact.
#define MERGE3(a0,a1,a2,b0,b1,b2,c0,c1,c2) do {      \
    c0 = fminf(a0, b0);                              \
    float _x = fmaxf(a0, b0);                        \
    c1 = fminf(_x, fminf(a1, b1));                   \
    c2 = fminf(fminf(a2, b2),                        \
               fminf(fmaxf(a1, b0), fmaxf(a0, b1))); \
} while (0)

// Lexicographic u64-key insert into 3 smallest.
__device__ __forceinline__ void kins(unsigned long long key,
    unsigned long long& q0, unsigned long long& q1, unsigned long long& q2) {
    bool b0 = key < q0, b1 = key < q1, b2 = key < q2;
    unsigned long long n2 = b1 ? q1 : (b2 ? key : q2);
    unsigned long long n1 = b0 ? q0 : (b1 ? key : q1);
    q0 = b0 ? key : q0;
    q1 = n1; q2 = n2;
}

// (value,index) lex insert for slow path.
__device__ __forceinline__ void ins_lex(float d, int k,
    float& d0, int& k0, float& d1, int& k1, float& d2, int& k2) {
    bool b0 = (d < d0) || (d == d0 && k < k0);
    bool b1 = (d < d1) || (d == d1 && k < k1);
    bool b2 = (d < d2) || (d == d2 && k < k2);
    float nd2 = b1 ? d1 : (b2 ? d : d2);  int nk2 = b1 ? k1 : (b2 ? k : k2);
    float nd1 = b0 ? d0 : (b1 ? d : d1);  int nk1 = b0 ? k0 : (b1 ? k : k1);
    d0 = b0 ? d : d0;  k0 = b0 ? k : k0;
    d1 = nd1; k1 = nk1; d2 = nd2; k2 = nk2;
}

__global__ __launch_bounds__(128, 12)
void interp_kernel(const float* __restrict__ x,
                   const float* __restrict__ mask,
                   const float* __restrict__ dist,
                   const int*   __restrict__ nh_idx,
                   float*       __restrict__ out) {
    __shared__ unsigned long long slist[NT][CAP];    // warp-private recovery lists
    __shared__ int scnt[NT];

    const int c    = blockIdx.x;
    const int tid  = threadIdx.x;
    const int lane = tid & 31;
    const int w    = tid >> 5;
    const int t    = w * 4 + (lane >> 3);   // 8 lanes per target, warp-aligned
    const int sub  = lane & 7;

    if (tid < NT) scnt[tid] = 0;

    // ---- dist candidates straight into registers (coalesced float4) ----
    const float4* drow4 = (const float4*)(dist + (size_t)c * (NT * KC) + t * KC);
    float4 v0 = drow4[sub];
    float4 v1 = drow4[sub + 8];
    float4 v2 = drow4[sub + 16];
    float4 v3 = drow4[sub + 24];
    float4 v4 = make_float4(BIG, BIG, BIG, BIG);
    if (sub < 4) v4 = drow4[sub + 32];

    // ---- mask-zero check only (no feature staging) ----
    bool any = false;
    const float4* m4p = (const float4*)mask;
    #pragma unroll
    for (int i = tid; i < KC; i += 128) {
        int nc = nh_idx[c * NH_SZ + (i >> 4)];
        float4 mv = m4p[nc * 16 + (i & 15)];
        any |= (mv.x != 0.f) | (mv.y != 0.f) | (mv.z != 0.f) | (mv.w != 0.f);
    }

    // ---- speculative value-only scan, 4 ILP streams ----
    float ax = BIG, bx = BIG, cx = BIG;
    float ay = BIG, by = BIG, cy = BIG;
    float az = BIG, bz = BIG, cz = BIG;
    float aw = BIG, bw = BIG, cw = BIG;
    VINS(v0.x, ax, bx, cx); VINS(v0.y, ay, by, cy);
    VINS(v0.z, az, bz, cz); VINS(v0.w, aw, bw, cw);
    VINS(v1.x, ax, bx, cx); VINS(v1.y, ay, by, cy);
    VINS(v1.z, az, bz, cz); VINS(v1.w, aw, bw, cw);
    VINS(v2.x, ax, bx, cx); VINS(v2.y, ay, by, cy);
    VINS(v2.z, az, bz, cz); VINS(v2.w, aw, bw, cw);
    VINS(v3.x, ax, bx, cx); VINS(v3.y, ay, by, cy);
    VINS(v3.z, az, bz, cz); VINS(v3.w, aw, bw, cw);
    VINS(v4.x, ax, bx, cx); VINS(v4.y, ay, by, cy);
    VINS(v4.z, az, bz, cz); VINS(v4.w, aw, bw, cw);

    float mx0, mx1, mx2, my0, my1, my2;
    MERGE3(ax, bx, cx, ay, by, cy, mx0, mx1, mx2);
    MERGE3(az, bz, cz, aw, bw, cw, my0, my1, my2);
    float d0, d1, d2;
    MERGE3(mx0, mx1, mx2, my0, my1, my2, d0, d1, d2);

    // ---- merge across the 8 threads of this target ----
    #pragma unroll
    for (int m = 1; m < 8; m <<= 1) {
        float p0 = __shfl_xor_sync(0xffffffffu, d0, m);
        float p1 = __shfl_xor_sync(0xffffffffu, d1, m);
        float p2 = __shfl_xor_sync(0xffffffffu, d2, m);
        float e0, e1, e2;
        MERGE3(d0, d1, d2, p0, p1, p2, e0, e1, e2);
        d0 = e0; d1 = e1; d2 = e2;
    }

    // single barrier: reduce the mask flag (also orders scnt init vs pushes)
    int bad = __syncthreads_or(any ? 1 : 0);

    if (!bad) {
        // ================= FAST PATH (mask == 0) =================
        // exact index recovery: per-component predicated pushes of all
        // candidates <= exact 3rd-smallest (values referenced BY NAME).
        #define TRYC(val, kk) do {                                           \
            if ((val) <= d2) {                                               \
                int _i = atomicAdd(&scnt[t], 1);                             \
                if (_i < CAP)                                                \
                    slist[t][_i] = ((unsigned long long)__float_as_uint(val) \
                                    << 8) | (unsigned)(kk);                  \
            } } while (0)
        const int kb = 4 * sub;
        TRYC(v0.x, kb);       TRYC(v0.y, kb + 1);
        TRYC(v0.z, kb + 2);   TRYC(v0.w, kb + 3);
        TRYC(v1.x, kb + 32);  TRYC(v1.y, kb + 33);
        TRYC(v1.z, kb + 34);  TRYC(v1.w, kb + 35);
        TRYC(v2.x, kb + 64);  TRYC(v2.y, kb + 65);
        TRYC(v2.z, kb + 66);  TRYC(v2.w, kb + 67);
        TRYC(v3.x, kb + 96);  TRYC(v3.y, kb + 97);
        TRYC(v3.z, kb + 98);  TRYC(v3.w, kb + 99);
        if (sub < 4) {
            TRYC(v4.x, kb + 128); TRYC(v4.y, kb + 129);
            TRYC(v4.z, kb + 130); TRYC(v4.w, kb + 131);
        }
        #undef TRYC
        __syncwarp();   // pushes for target t all come from this warp

        if (sub < NV) {
            const int v = sub;
            int n = scnt[t];
            unsigned long long q0 = ~0ull, q1 = ~0ull, q2 = ~0ull;
            if (n <= CAP) {
                for (int i = 0; i < n; i++)
                    kins(slist[t][i], q0, q1, q2);
            } else {
                // degenerate tie overflow: exact full rescan from global
                const float* row = dist + (size_t)c * (NT * KC) + t * KC;
                for (int k = 0; k < KC; k++) {
                    unsigned long long key =
                        ((unsigned long long)__float_as_uint(row[k]) << 8)
                        | (unsigned)k;
                    kins(key, q0, q1, q2);
                }
            }
            float f0 = __uint_as_float((unsigned)(q0 >> 8));
            float f1 = __uint_as_float((unsigned)(q1 >> 8));
            float f2 = __uint_as_float((unsigned)(q2 >> 8));
            int   i0 = (int)(q0 & 0xFF), i1 = (int)(q1 & 0xFF),
                  i2 = (int)(q2 & 0xFF);

            // direct global feature loads (nh_idx / x are L1/L2-hot)
            const int* nh = nh_idx + c * NH_SZ;
            float g0 = x[(nh[i0 >> 4] * 16 + (i0 & 15)) * NV + v];
            float g1 = x[(nh[i1 >> 4] * 16 + (i1 & 15)) * NV + v];
            float g2 = x[(nh[i2 >> 4] * 16 + (i2 & 15)) * NV + v];

            float c0 = fmaxf(f0, CUTOFF_DIST);
            float c1 = fmaxf(f1, CUTOFF_DIST);
            float c2 = fmaxf(f2, CUTOFF_DIST);
            float w0 = c1 * c2, w1 = c0 * c2, w2 = c0 * c1;
            w0 *= w0; w1 *= w1; w2 *= w2;
            out[(size_t)c * (NT * NV) + t * NV + v] =
                (g0 * w0 + g1 * w1 + g2 * w2) / (w0 + w1 + w2);
        }
    } else {
        // ================= SLOW PATH (general mask) =================
        if (tid < NT * NV) {
            const int tt = tid >> 2;
            const int v  = tid & 3;
            const float* dr = dist + (size_t)c * (NT * KC) + tt * KC;
            const int* nh = nh_idx + c * NH_SZ;
            float s0 = BIG, s1 = BIG, s2 = BIG;
            int   k0 = 0,   k1 = 0,   k2 = 0;
            for (int k = 0; k < KC; k++) {
                int nc = nh[k >> 4];
                float mk = mask[(nc * 16 + (k & 15)) * NV + v] * MASK_VALUE;
                float d  = dr[k] + mk;
                ins_lex(d, k, s0, k0, s1, k1, s2, k2);
            }
            float c0 = fmaxf(s0, CUTOFF_DIST);
            float c1 = fmaxf(s1, CUTOFF_DIST);
            float c2 = fmaxf(s2, CUTOFF_DIST);
            float w0 = c1 * c2, w1 = c0 * c2, w2 = c0 * c1;
            w0 *= w0; w1 *= w1; w2 *= w2;
            float g0 = x[(nh[k0 >> 4] * 16 + (k0 & 15)) * NV + v];
            float g1 = x[(nh[k1 >> 4] * 16 + (k1 & 15)) * NV + v];
            float g2 = x[(nh[k2 >> 4] * 16 + (k2 & 15)) * NV + v];
            out[(size_t)c * (NT * NV) + tt * NV + v] =
                (g0 * w0 + g1 * w1 + g2 * w2) / (w0 + w1 + w2);
        }
    }
}

extern "C" void kernel_launch(void* const* d_in, const int* in_sizes, int n_in,
                              void* d_out, int out_size) {
    const float* x      = (const float*)d_in[0];
    const float* mask   = (const float*)d_in[1];
    const float* dist   = (const float*)d_in[2];
    const int*   nh_idx = (const int*)  d_in[3];
    float*       out    = (float*)d_out;

    interp_kernel<<<N_L, 128>>>(x, mask, dist, nh_idx, out);
}